// round 13
// baseline (speedup 1.0000x reference)
#include <cuda_runtime.h>
#include <cuda_fp16.h>
#include <stdint.h>

// LSTM_558345748830 v12: duplicate-mma / split-activation.
// Block = 256 threads = 8 warps, 16 batches. Warps w and w+4 share gate family
// f=w&3 (ntiles {f,f+4,f+8,f+12}; ntile==gate) and both run the SAME mma; each
// handles activations/stores for only half the batch rows (hh = w>>2).
// => 4 warps/SMSP feeding the binding MUFU pipe, total MUFU work unchanged.
// B-fragments live in shared (deduped across duplicate warps) to fit 2 blocks/SM.

#define Tn 512
#define Hn 32
#define NB 16
#define NT 256
#define Bn 4096

__device__ __forceinline__ float tanhap(float x) {
    float y;
    asm("tanh.approx.f32 %0, %1;" : "=f"(y) : "f"(x));
    return y;
}
__device__ __forceinline__ float sigap(float x) {
    return fmaf(tanhap(0.5f * x), 0.5f, 0.5f);
}
__device__ __forceinline__ void mma_f16(float* d, const uint32_t* a, const uint32_t* b) {
    asm volatile(
        "mma.sync.aligned.m16n8k16.row.col.f32.f16.f16.f32 "
        "{%0,%1,%2,%3}, {%4,%5,%6,%7}, {%8,%9}, {%0,%1,%2,%3};"
        : "+f"(d[0]), "+f"(d[1]), "+f"(d[2]), "+f"(d[3])
        : "r"(a[0]), "r"(a[1]), "r"(a[2]), "r"(a[3]), "r"(b[0]), "r"(b[1]));
}
// pack {even-k -> low half, odd-k -> high half}
__device__ __forceinline__ uint32_t pack2(float e_even, float e_odd) {
    uint32_t r;
    asm("cvt.rn.f16x2.f32 %0, %1, %2;" : "=r"(r) : "f"(e_odd), "f"(e_even));
    return r;
}

__global__ __launch_bounds__(NT, 2)
void lstm_tc10(const float* __restrict__ x,
               const float* __restrict__ w_ih_0, const float* __restrict__ w_hh_0,
               const float* __restrict__ b_ih_0, const float* __restrict__ b_hh_0,
               const float* __restrict__ w_ih_1, const float* __restrict__ w_hh_1,
               const float* __restrict__ b_ih_1, const float* __restrict__ b_hh_1,
               const float* __restrict__ fc_w,   const float* __restrict__ fc_b,
               float* __restrict__ out)
{
    __shared__ uint32_t frag[2][512];   // [buf][(kt*4+r)*32+lane]; kt0-1=h1, kt2-3=h2
    __shared__ uint2 b1s[4 * 4 * 2 * 32];  // [((f*4+nt)*2+kt)*32+lane]  (8 KB)
    __shared__ uint2 b2s[4 * 4 * 4 * 32];  // [((f*4+nt)*4+kt)*32+lane]  (16 KB)
    __shared__ float hf[NB][Hn + 1];       // final h2 for FC head

    const int tid  = threadIdx.x;
    const int lane = tid & 31;
    const int w    = tid >> 5;        // warp 0..7
    const int f    = w & 3;           // gate family (ntiles f+4k)
    const int hh   = w >> 2;          // row half: 0 -> rows g, 1 -> rows g+8
    const int g    = lane >> 2;
    const int t4   = lane & 3;
    const int pp   = hh * 2;          // acc parity base for this half
    const int row  = g + 8 * hh;      // batch row this thread owns
    const int jcol = 8 * f + 2 * t4;  // hidden-unit column pair
    const int b0   = blockIdx.x * NB;
    const float* xg = x + (size_t)b0 * Tn;

    for (int i = tid; i < 2 * 512; i += NT) (&frag[0][0])[i] = 0u;

    // ---- build B-fragments in shared (half-0 warps only; deduped) ----
    if (hh == 0) {
        #pragma unroll
        for (int nt = 0; nt < 4; nt++) {
            const int n = (f + 4 * nt) * 8 + g;       // global gate row
            const float* w0 = w_hh_0 + n * Hn;
            #pragma unroll
            for (int kt = 0; kt < 2; kt++) {
                uint2 v;
                { int k = kt * 16 + 2 * t4;     v.x = pack2(w0[k], w0[k + 1]); }
                { int k = kt * 16 + 2 * t4 + 8; v.y = pack2(w0[k], w0[k + 1]); }
                b1s[((f * 4 + nt) * 2 + kt) * 32 + lane] = v;
            }
            const float* wi1 = w_ih_1 + n * Hn;
            const float* wh1 = w_hh_1 + n * Hn;
            #pragma unroll
            for (int kt = 0; kt < 4; kt++) {
                const float* ws = (kt < 2) ? (wi1 + kt * 16) : (wh1 + (kt - 2) * 16);
                uint2 v;
                { int k = 2 * t4;     v.x = pack2(ws[k], ws[k + 1]); }
                { int k = 2 * t4 + 8; v.y = pack2(ws[k], ws[k + 1]); }
                b2s[((f * 4 + nt) * 4 + kt) * 32 + lane] = v;
            }
        }
    }

    // ---- epilogue constants per (gate nt, parity) — column-indexed only ----
    float wx[8], bi0[8], bi1[8];
    #pragma unroll
    for (int q = 0; q < 8; q++) {
        int n = (f + 4 * (q >> 1)) * 8 + 2 * t4 + (q & 1);
        wx[q]  = w_ih_0[n];
        bi0[q] = b_ih_0[n] + b_hh_0[n];
        bi1[q] = b_ih_1[n] + b_hh_1[n];
    }

    // frag store slot for (row, jcol): layer-1 base; +32 for row g+8; +256 layer-2
    const int slf = (((f >> 1) * 4) + (f & 1) * 2) * 32 + lane + hh * 32;

    float g1acc[4][4], g2acc[4][4];   // [gate][p]; only p = pp, pp+1 meaningful
    float c1[2] = {0.f, 0.f}, c2[2] = {0.f, 0.f};

    // ---- prologue: gates1(0) -> h1(0) -> frag[0] (own half only) ----
    {
        const float xv = __ldg(&xg[row * Tn]);
        float h1v[2];
        #pragma unroll
        for (int i = 0; i < 2; i++) {
            float acc[4];
            #pragma unroll
            for (int nt = 0; nt < 4; nt++)
                acc[nt] = fmaf(wx[nt * 2 + i], xv, bi0[nt * 2 + i]);
            float i_ = sigap(acc[0]);
            float f_ = sigap(acc[1]);
            float g_ = tanhap(acc[2]);
            float o_ = sigap(acc[3]);
            c1[i] = fmaf(f_, c1[i], i_ * g_);
            h1v[i] = o_ * tanhap(c1[i]);
        }
        frag[0][slf] = pack2(h1v[0], h1v[1]);
        // h2(-1) region already zero
    }
    __syncthreads();

    // ---- one fused phase; buf literal -> constant frag addrs ----
    auto phase = [&](const int t, const int buf) {
        const bool last = (t == Tn - 1);
        uint32_t Ah[4][4];
        #pragma unroll
        for (int kt = 0; kt < 4; kt++)
            #pragma unroll
            for (int r = 0; r < 4; r++)
                Ah[kt][r] = frag[buf][(kt * 4 + r) * 32 + lane];

        if (!last) {   // gates1(t+1): init own half with x-term, other half 0
            const float xv = __ldg(&xg[row * Tn + t + 1]);
            #pragma unroll
            for (int nt = 0; nt < 4; nt++) {
                g1acc[nt][pp + 0]       = fmaf(wx[nt * 2 + 0], xv, bi0[nt * 2 + 0]);
                g1acc[nt][pp + 1]       = fmaf(wx[nt * 2 + 1], xv, bi0[nt * 2 + 1]);
                g1acc[nt][(pp ^ 2) + 0] = 0.f;
                g1acc[nt][(pp ^ 2) + 1] = 0.f;
                #pragma unroll
                for (int kt = 0; kt < 2; kt++) {
                    uint2 bb = b1s[((f * 4 + nt) * 2 + kt) * 32 + lane];
                    uint32_t br[2] = {bb.x, bb.y};
                    mma_f16(g1acc[nt], Ah[kt], br);
                }
            }
        }
        // gates2(t)
        #pragma unroll
        for (int nt = 0; nt < 4; nt++) {
            g2acc[nt][pp + 0]       = bi1[nt * 2 + 0];
            g2acc[nt][pp + 1]       = bi1[nt * 2 + 1];
            g2acc[nt][(pp ^ 2) + 0] = 0.f;
            g2acc[nt][(pp ^ 2) + 1] = 0.f;
            #pragma unroll
            for (int kt = 0; kt < 4; kt++) {
                uint2 bb = b2s[((f * 4 + nt) * 4 + kt) * 32 + lane];
                uint32_t br[2] = {bb.x, bb.y};
                mma_f16(g2acc[nt], Ah[kt], br);
            }
        }
        if (!last) {   // h1(t+1), own half
            float h1v[2];
            #pragma unroll
            for (int i = 0; i < 2; i++) {
                const int p = pp + i;
                float i_ = sigap(g1acc[0][p]);
                float f_ = sigap(g1acc[1][p]);
                float g_ = tanhap(g1acc[2][p]);
                float o_ = sigap(g1acc[3][p]);
                c1[i] = fmaf(f_, c1[i], i_ * g_);
                h1v[i] = o_ * tanhap(c1[i]);
            }
            frag[buf ^ 1][slf] = pack2(h1v[0], h1v[1]);
        }
        {   // h2(t), own half
            float h2v[2];
            #pragma unroll
            for (int i = 0; i < 2; i++) {
                const int p = pp + i;
                float i_ = sigap(g2acc[0][p]);
                float f_ = sigap(g2acc[1][p]);
                float g_ = tanhap(g2acc[2][p]);
                float o_ = sigap(g2acc[3][p]);
                c2[i] = fmaf(f_, c2[i], i_ * g_);
                h2v[i] = o_ * tanhap(c2[i]);
            }
            if (!last) {
                frag[buf ^ 1][slf + 256] = pack2(h2v[0], h2v[1]);
            } else {
                hf[row][jcol + 0] = h2v[0];
                hf[row][jcol + 1] = h2v[1];
            }
        }
        __syncthreads();
    };

    for (int t = 0; t < Tn; t += 2) {
        phase(t, 0);
        phase(t + 1, 1);
    }

    // ---- FC head ----
    if (tid < NB) {
        float a = fc_b[0];
        #pragma unroll
        for (int k = 0; k < Hn; k++) a = fmaf(hf[tid][k], fc_w[k], a);
        out[b0 + tid] = a;
    }
}

extern "C" void kernel_launch(void* const* d_in, const int* in_sizes, int n_in,
                              void* d_out, int out_size)
{
    (void)in_sizes; (void)n_in; (void)out_size;
    const float* x      = (const float*)d_in[0];
    const float* w_ih_0 = (const float*)d_in[1];
    const float* w_hh_0 = (const float*)d_in[2];
    const float* b_ih_0 = (const float*)d_in[3];
    const float* b_hh_0 = (const float*)d_in[4];
    const float* w_ih_1 = (const float*)d_in[5];
    const float* w_hh_1 = (const float*)d_in[6];
    const float* b_ih_1 = (const float*)d_in[7];
    const float* b_hh_1 = (const float*)d_in[8];
    const float* fc_w   = (const float*)d_in[9];
    const float* fc_b   = (const float*)d_in[10];
    float* o = (float*)d_out;

    dim3 grid(Bn / NB);   // 256 blocks x 256 thr -> 2 blocks/SM, single wave
    dim3 block(NT);
    lstm_tc10<<<grid, block>>>(x, w_ih_0, w_hh_0, b_ih_0, b_hh_0,
                               w_ih_1, w_hh_1, b_ih_1, b_hh_1,
                               fc_w, fc_b, o);
}

// round 14
// speedup vs baseline: 1.0310x; 1.0310x over previous
#include <cuda_runtime.h>
#include <cuda_fp16.h>
#include <stdint.h>

// LSTM_558345748830 v13: duplicate-mma / split-activation, spill-free.
// Block = 256 threads = 8 warps, 16 batches. Warps w and w+4 share gate family
// f=w&3 and run the SAME mma; each handles activations for half the rows.
// Register diet vs v12: epilogue constants in shared, Ah split into two 8-reg
// halves, B-fragments in shared. Target: fit 128 regs with ZERO spills.

#define Tn 512
#define Hn 32
#define NB 16
#define NT 256
#define Bn 4096

__device__ __forceinline__ float tanhap(float x) {
    float y;
    asm("tanh.approx.f32 %0, %1;" : "=f"(y) : "f"(x));
    return y;
}
__device__ __forceinline__ float sigap(float x) {
    return fmaf(tanhap(0.5f * x), 0.5f, 0.5f);
}
__device__ __forceinline__ void mma_f16(float* d, const uint32_t* a, const uint32_t* b) {
    asm volatile(
        "mma.sync.aligned.m16n8k16.row.col.f32.f16.f16.f32 "
        "{%0,%1,%2,%3}, {%4,%5,%6,%7}, {%8,%9}, {%0,%1,%2,%3};"
        : "+f"(d[0]), "+f"(d[1]), "+f"(d[2]), "+f"(d[3])
        : "r"(a[0]), "r"(a[1]), "r"(a[2]), "r"(a[3]), "r"(b[0]), "r"(b[1]));
}
// pack {even-k -> low half, odd-k -> high half}
__device__ __forceinline__ uint32_t pack2(float e_even, float e_odd) {
    uint32_t r;
    asm("cvt.rn.f16x2.f32 %0, %1, %2;" : "=r"(r) : "f"(e_odd), "f"(e_even));
    return r;
}

__global__ __launch_bounds__(NT, 2)
void lstm_tc11(const float* __restrict__ x,
               const float* __restrict__ w_ih_0, const float* __restrict__ w_hh_0,
               const float* __restrict__ b_ih_0, const float* __restrict__ b_hh_0,
               const float* __restrict__ w_ih_1, const float* __restrict__ w_hh_1,
               const float* __restrict__ b_ih_1, const float* __restrict__ b_hh_1,
               const float* __restrict__ fc_w,   const float* __restrict__ fc_b,
               float* __restrict__ out)
{
    __shared__ uint32_t frag[2][512];      // [buf][(kt*4+r)*32+lane]
    __shared__ uint2  b1s[4 * 4 * 2 * 32]; // [((f*4+nt)*2+kt)*32+lane]
    __shared__ uint2  b2s[4 * 4 * 4 * 32]; // [((f*4+nt)*4+kt)*32+lane]
    __shared__ float2 wb0s[4 * Hn];        // per gate-row: (w_ih_0, b_ih_0+b_hh_0)
    __shared__ float  bi1s[4 * Hn];        // per gate-row: b_ih_1+b_hh_1
    __shared__ float  hf[NB][Hn + 1];      // final h2 for FC head

    const int tid  = threadIdx.x;
    const int lane = tid & 31;
    const int w    = tid >> 5;        // warp 0..7
    const int f    = w & 3;           // gate family (ntiles f+4k)
    const int hh   = w >> 2;          // row half: 0 -> rows g, 1 -> rows g+8
    const int g    = lane >> 2;
    const int t4   = lane & 3;
    const int pp   = hh * 2;          // acc parity base for this half
    const int row  = g + 8 * hh;      // batch row this thread owns
    const int jcol = 8 * f + 2 * t4;  // hidden-unit column pair
    const int b0   = blockIdx.x * NB;
    const float* xg = x + (size_t)b0 * Tn;

    for (int i = tid; i < 2 * 512; i += NT) (&frag[0][0])[i] = 0u;

    // ---- B-fragments into shared (half-0 warps only; deduped) ----
    if (hh == 0) {
        #pragma unroll
        for (int nt = 0; nt < 4; nt++) {
            const int n = (f + 4 * nt) * 8 + g;       // global gate row
            const float* w0 = w_hh_0 + n * Hn;
            #pragma unroll
            for (int kt = 0; kt < 2; kt++) {
                uint2 v;
                { int k = kt * 16 + 2 * t4;     v.x = pack2(w0[k], w0[k + 1]); }
                { int k = kt * 16 + 2 * t4 + 8; v.y = pack2(w0[k], w0[k + 1]); }
                b1s[((f * 4 + nt) * 2 + kt) * 32 + lane] = v;
            }
            const float* wi1 = w_ih_1 + n * Hn;
            const float* wh1 = w_hh_1 + n * Hn;
            #pragma unroll
            for (int kt = 0; kt < 4; kt++) {
                const float* ws = (kt < 2) ? (wi1 + kt * 16) : (wh1 + (kt - 2) * 16);
                uint2 v;
                { int k = 2 * t4;     v.x = pack2(ws[k], ws[k + 1]); }
                { int k = 2 * t4 + 8; v.y = pack2(ws[k], ws[k + 1]); }
                b2s[((f * 4 + nt) * 4 + kt) * 32 + lane] = v;
            }
        }
    }
    // ---- epilogue constants into shared ----
    for (int i = tid; i < 4 * Hn; i += NT) {
        wb0s[i] = make_float2(w_ih_0[i], b_ih_0[i] + b_hh_0[i]);
        bi1s[i] = b_ih_1[i] + b_hh_1[i];
    }
    __syncthreads();

    // frag store slot for (row, jcol); +256 = layer-2 region
    const int slf = (((f >> 1) * 4) + (f & 1) * 2) * 32 + lane + hh * 32;

    float g1acc[4][4], g2acc[4][4];   // [gate][p]; only p = pp, pp+1 meaningful
    float c1[2] = {0.f, 0.f}, c2[2] = {0.f, 0.f};

    // ---- prologue: gates1(0) -> h1(0) -> frag[0] (own half only) ----
    {
        const float xv = __ldg(&xg[row * Tn]);
        float h1v[2];
        #pragma unroll
        for (int i = 0; i < 2; i++) {
            float acc[4];
            #pragma unroll
            for (int nt = 0; nt < 4; nt++) {
                float2 wb = wb0s[(f + 4 * nt) * 8 + 2 * t4 + i];
                acc[nt] = fmaf(wb.x, xv, wb.y);
            }
            float i_ = sigap(acc[0]);
            float f_ = sigap(acc[1]);
            float g_ = tanhap(acc[2]);
            float o_ = sigap(acc[3]);
            c1[i] = fmaf(f_, c1[i], i_ * g_);
            h1v[i] = o_ * tanhap(c1[i]);
        }
        frag[0][slf] = pack2(h1v[0], h1v[1]);
        // h2(-1) region already zero
    }
    __syncthreads();

    // ---- one fused phase; buf literal -> constant frag addrs ----
    auto phase = [&](const int t, const int buf) {
        const bool last = (t == Tn - 1);
        uint32_t Ah[2][4];                 // two ktiles at a time (8 regs)
        #pragma unroll
        for (int kt = 0; kt < 2; kt++)
            #pragma unroll
            for (int r = 0; r < 4; r++)
                Ah[kt][r] = frag[buf][(kt * 4 + r) * 32 + lane];

        if (!last) {   // gates1(t+1): own half init with x-term, other half 0
            const float xv = __ldg(&xg[row * Tn + t + 1]);
            #pragma unroll
            for (int nt = 0; nt < 4; nt++) {
                float2 wbA = wb0s[(f + 4 * nt) * 8 + 2 * t4 + 0];
                float2 wbB = wb0s[(f + 4 * nt) * 8 + 2 * t4 + 1];
                g1acc[nt][pp + 0]       = fmaf(wbA.x, xv, wbA.y);
                g1acc[nt][pp + 1]       = fmaf(wbB.x, xv, wbB.y);
                g1acc[nt][(pp ^ 2) + 0] = 0.f;
                g1acc[nt][(pp ^ 2) + 1] = 0.f;
                #pragma unroll
                for (int kt = 0; kt < 2; kt++) {
                    uint2 bb = b1s[((f * 4 + nt) * 2 + kt) * 32 + lane];
                    uint32_t br[2] = {bb.x, bb.y};
                    mma_f16(g1acc[nt], Ah[kt], br);
                }
            }
        }
        // gates2(t), ktiles 0-1 (h1 part)
        #pragma unroll
        for (int nt = 0; nt < 4; nt++) {
            g2acc[nt][pp + 0]       = bi1s[(f + 4 * nt) * 8 + 2 * t4 + 0];
            g2acc[nt][pp + 1]       = bi1s[(f + 4 * nt) * 8 + 2 * t4 + 1];
            g2acc[nt][(pp ^ 2) + 0] = 0.f;
            g2acc[nt][(pp ^ 2) + 1] = 0.f;
            #pragma unroll
            for (int kt = 0; kt < 2; kt++) {
                uint2 bb = b2s[((f * 4 + nt) * 4 + kt) * 32 + lane];
                uint32_t br[2] = {bb.x, bb.y};
                mma_f16(g2acc[nt], Ah[kt], br);
            }
        }
        // reload Ah with ktiles 2-3 (h2 part), finish gates2
        #pragma unroll
        for (int kt = 0; kt < 2; kt++)
            #pragma unroll
            for (int r = 0; r < 4; r++)
                Ah[kt][r] = frag[buf][((kt + 2) * 4 + r) * 32 + lane];
        #pragma unroll
        for (int nt = 0; nt < 4; nt++) {
            #pragma unroll
            for (int kt = 0; kt < 2; kt++) {
                uint2 bb = b2s[((f * 4 + nt) * 4 + kt + 2) * 32 + lane];
                uint32_t br[2] = {bb.x, bb.y};
                mma_f16(g2acc[nt], Ah[kt], br);
            }
        }

        if (!last) {   // h1(t+1), own half
            float h1v[2];
            #pragma unroll
            for (int i = 0; i < 2; i++) {
                const int p = pp + i;
                float i_ = sigap(g1acc[0][p]);
                float f_ = sigap(g1acc[1][p]);
                float g_ = tanhap(g1acc[2][p]);
                float o_ = sigap(g1acc[3][p]);
                c1[i] = fmaf(f_, c1[i], i_ * g_);
                h1v[i] = o_ * tanhap(c1[i]);
            }
            frag[buf ^ 1][slf] = pack2(h1v[0], h1v[1]);
        }
        {   // h2(t), own half
            float h2v[2];
            #pragma unroll
            for (int i = 0; i < 2; i++) {
                const int p = pp + i;
                float i_ = sigap(g2acc[0][p]);
                float f_ = sigap(g2acc[1][p]);
                float g_ = tanhap(g2acc[2][p]);
                float o_ = sigap(g2acc[3][p]);
                c2[i] = fmaf(f_, c2[i], i_ * g_);
                h2v[i] = o_ * tanhap(c2[i]);
            }
            if (!last) {
                frag[buf ^ 1][slf + 256] = pack2(h2v[0], h2v[1]);
            } else {
                hf[row][jcol + 0] = h2v[0];
                hf[row][jcol + 1] = h2v[1];
            }
        }
        __syncthreads();
    };

    for (int t = 0; t < Tn; t += 2) {
        phase(t, 0);
        phase(t + 1, 1);
    }

    // ---- FC head ----
    if (tid < NB) {
        float a = fc_b[0];
        #pragma unroll
        for (int k = 0; k < Hn; k++) a = fmaf(hf[tid][k], fc_w[k], a);
        out[b0 + tid] = a;
    }
}

extern "C" void kernel_launch(void* const* d_in, const int* in_sizes, int n_in,
                              void* d_out, int out_size)
{
    (void)in_sizes; (void)n_in; (void)out_size;
    const float* x      = (const float*)d_in[0];
    const float* w_ih_0 = (const float*)d_in[1];
    const float* w_hh_0 = (const float*)d_in[2];
    const float* b_ih_0 = (const float*)d_in[3];
    const float* b_hh_0 = (const float*)d_in[4];
    const float* w_ih_1 = (const float*)d_in[5];
    const float* w_hh_1 = (const float*)d_in[6];
    const float* b_ih_1 = (const float*)d_in[7];
    const float* b_hh_1 = (const float*)d_in[8];
    const float* fc_w   = (const float*)d_in[9];
    const float* fc_b   = (const float*)d_in[10];
    float* o = (float*)d_out;

    dim3 grid(Bn / NB);   // 256 blocks x 256 thr -> 2 blocks/SM, single wave
    dim3 block(NT);
    lstm_tc11<<<grid, block>>>(x, w_ih_0, w_hh_0, b_ih_0, b_hh_0,
                               w_ih_1, w_hh_1, b_ih_1, b_hh_1,
                               fc_w, fc_b, o);
}

// round 15
// speedup vs baseline: 3.1417x; 3.0473x over previous
#include <cuda_runtime.h>
#include <cuda_fp16.h>
#include <stdint.h>

// LSTM_558345748830 v14: duplicate-mma / split-activation, LOCAL-MEMORY-FREE.
// Block = 256 threads = 8 warps, 16 batches. Warps w and w+4 share gate family
// f=w&3 and run the SAME mma; each handles activations for half the rows
// (hh = w>>2). v12/v13 died because acc arrays were indexed by runtime pp ->
// demoted to local memory. Here EVERY accumulator index is a literal: one
// warp-uniform branch on hh selects the {0,1} or {2,3} accumulator elements.

#define Tn 512
#define Hn 32
#define NB 16
#define NT 256
#define Bn 4096

__device__ __forceinline__ float tanhap(float x) {
    float y;
    asm("tanh.approx.f32 %0, %1;" : "=f"(y) : "f"(x));
    return y;
}
__device__ __forceinline__ float sigap(float x) {
    return fmaf(tanhap(0.5f * x), 0.5f, 0.5f);
}
__device__ __forceinline__ void mma_f16(float* d, const uint32_t* a, const uint32_t* b) {
    asm volatile(
        "mma.sync.aligned.m16n8k16.row.col.f32.f16.f16.f32 "
        "{%0,%1,%2,%3}, {%4,%5,%6,%7}, {%8,%9}, {%0,%1,%2,%3};"
        : "+f"(d[0]), "+f"(d[1]), "+f"(d[2]), "+f"(d[3])
        : "r"(a[0]), "r"(a[1]), "r"(a[2]), "r"(a[3]), "r"(b[0]), "r"(b[1]));
}
// pack {even-k -> low half, odd-k -> high half}
__device__ __forceinline__ uint32_t pack2(float e_even, float e_odd) {
    uint32_t r;
    asm("cvt.rn.f16x2.f32 %0, %1, %2;" : "=r"(r) : "f"(e_odd), "f"(e_even));
    return r;
}

__global__ __launch_bounds__(NT, 2)
void lstm_tc12(const float* __restrict__ x,
               const float* __restrict__ w_ih_0, const float* __restrict__ w_hh_0,
               const float* __restrict__ b_ih_0, const float* __restrict__ b_hh_0,
               const float* __restrict__ w_ih_1, const float* __restrict__ w_hh_1,
               const float* __restrict__ b_ih_1, const float* __restrict__ b_hh_1,
               const float* __restrict__ fc_w,   const float* __restrict__ fc_b,
               float* __restrict__ out)
{
    __shared__ uint32_t frag[2][512];      // [buf][(kt*4+r)*32+lane]
    __shared__ uint2  b1s[4 * 4 * 2 * 32]; // [((f*4+nt)*2+kt)*32+lane]
    __shared__ uint2  b2s[4 * 4 * 4 * 32]; // [((f*4+nt)*4+kt)*32+lane]
    __shared__ float  hf[NB][Hn + 1];      // final h2 for FC head

    const int tid  = threadIdx.x;
    const int lane = tid & 31;
    const int w    = tid >> 5;        // warp 0..7
    const int f    = w & 3;           // gate family (ntiles f+4k)
    const int hh   = w >> 2;          // row half: 0 -> rows g, 1 -> rows g+8
    const int g    = lane >> 2;
    const int t4   = lane & 3;
    const int row  = g + 8 * hh;      // batch row this thread owns
    const int jcol = 8 * f + 2 * t4;  // hidden-unit column pair
    const int b0   = blockIdx.x * NB;
    const float* xg = x + (size_t)b0 * Tn;

    for (int i = tid; i < 2 * 512; i += NT) (&frag[0][0])[i] = 0u;

    // ---- B-fragments into shared (half-0 warps only; deduped) ----
    if (hh == 0) {
        #pragma unroll
        for (int nt = 0; nt < 4; nt++) {
            const int n = (f + 4 * nt) * 8 + g;       // global gate row
            const float* w0 = w_hh_0 + n * Hn;
            #pragma unroll
            for (int kt = 0; kt < 2; kt++) {
                uint2 v;
                { int k = kt * 16 + 2 * t4;     v.x = pack2(w0[k], w0[k + 1]); }
                { int k = kt * 16 + 2 * t4 + 8; v.y = pack2(w0[k], w0[k + 1]); }
                b1s[((f * 4 + nt) * 2 + kt) * 32 + lane] = v;
            }
            const float* wi1 = w_ih_1 + n * Hn;
            const float* wh1 = w_hh_1 + n * Hn;
            #pragma unroll
            for (int kt = 0; kt < 4; kt++) {
                const float* ws = (kt < 2) ? (wi1 + kt * 16) : (wh1 + (kt - 2) * 16);
                uint2 v;
                { int k = 2 * t4;     v.x = pack2(ws[k], ws[k + 1]); }
                { int k = 2 * t4 + 8; v.y = pack2(ws[k], ws[k + 1]); }
                b2s[((f * 4 + nt) * 4 + kt) * 32 + lane] = v;
            }
        }
    }

    // ---- epilogue constants in registers (literal-indexed in unrolled code) ----
    float wx[8], bi0[8], bi1[8];
    #pragma unroll
    for (int q = 0; q < 8; q++) {
        int n = (f + 4 * (q >> 1)) * 8 + 2 * t4 + (q & 1);
        wx[q]  = w_ih_0[n];
        bi0[q] = b_ih_0[n] + b_hh_0[n];
        bi1[q] = b_ih_1[n] + b_hh_1[n];
    }

    // frag store slot for (row, jcol); +256 = layer-2 region
    const int slf = (((f >> 1) * 4) + (f & 1) * 2) * 32 + lane + hh * 32;

    float g1acc[4][4], g2acc[4][4];   // [gate][elem]; all indices literal
    float c1[2] = {0.f, 0.f}, c2[2] = {0.f, 0.f};

    // single-element LSTM cell update (all scalar, caller passes literal-indexed gates)
    auto ew1 = [&](float gi, float gf, float gg, float go, float& c) -> float {
        float i_ = sigap(gi);
        float f_ = sigap(gf);
        float g_ = tanhap(gg);
        float o_ = sigap(go);
        c = fmaf(f_, c, i_ * g_);
        return o_ * tanhap(c);
    };

    // ---- prologue: gates1(0) -> h1(0) -> frag[0] (own half only) ----
    {
        const float xv = __ldg(&xg[row * Tn]);
        float a0[4], a1[4];
        #pragma unroll
        for (int nt = 0; nt < 4; nt++) {
            a0[nt] = fmaf(wx[nt * 2 + 0], xv, bi0[nt * 2 + 0]);
            a1[nt] = fmaf(wx[nt * 2 + 1], xv, bi0[nt * 2 + 1]);
        }
        float h0 = ew1(a0[0], a0[1], a0[2], a0[3], c1[0]);
        float h1 = ew1(a1[0], a1[1], a1[2], a1[3], c1[1]);
        frag[0][slf] = pack2(h0, h1);
        // h2(-1) region already zero
    }
    __syncthreads();

    // ---- one fused phase; buf literal -> constant frag addrs ----
    auto phase = [&](const int t, const int buf) {
        const bool last = (t == Tn - 1);
        uint32_t Ah[4][4];
        #pragma unroll
        for (int kt = 0; kt < 4; kt++)
            #pragma unroll
            for (int r = 0; r < 4; r++)
                Ah[kt][r] = frag[buf][(kt * 4 + r) * 32 + lane];

        if (!last) {   // gates1(t+1): own half init with x-term, other half 0
            const float xv = __ldg(&xg[row * Tn + t + 1]);
            if (hh == 0) {
                #pragma unroll
                for (int nt = 0; nt < 4; nt++) {
                    g1acc[nt][0] = fmaf(wx[nt * 2 + 0], xv, bi0[nt * 2 + 0]);
                    g1acc[nt][1] = fmaf(wx[nt * 2 + 1], xv, bi0[nt * 2 + 1]);
                    g1acc[nt][2] = 0.f;
                    g1acc[nt][3] = 0.f;
                }
            } else {
                #pragma unroll
                for (int nt = 0; nt < 4; nt++) {
                    g1acc[nt][0] = 0.f;
                    g1acc[nt][1] = 0.f;
                    g1acc[nt][2] = fmaf(wx[nt * 2 + 0], xv, bi0[nt * 2 + 0]);
                    g1acc[nt][3] = fmaf(wx[nt * 2 + 1], xv, bi0[nt * 2 + 1]);
                }
            }
            #pragma unroll
            for (int nt = 0; nt < 4; nt++)
                #pragma unroll
                for (int kt = 0; kt < 2; kt++) {
                    uint2 bb = b1s[((f * 4 + nt) * 2 + kt) * 32 + lane];
                    uint32_t br[2] = {bb.x, bb.y};
                    mma_f16(g1acc[nt], Ah[kt], br);
                }
        }
        // gates2(t)
        if (hh == 0) {
            #pragma unroll
            for (int nt = 0; nt < 4; nt++) {
                g2acc[nt][0] = bi1[nt * 2 + 0];
                g2acc[nt][1] = bi1[nt * 2 + 1];
                g2acc[nt][2] = 0.f;
                g2acc[nt][3] = 0.f;
            }
        } else {
            #pragma unroll
            for (int nt = 0; nt < 4; nt++) {
                g2acc[nt][0] = 0.f;
                g2acc[nt][1] = 0.f;
                g2acc[nt][2] = bi1[nt * 2 + 0];
                g2acc[nt][3] = bi1[nt * 2 + 1];
            }
        }
        #pragma unroll
        for (int nt = 0; nt < 4; nt++)
            #pragma unroll
            for (int kt = 0; kt < 4; kt++) {
                uint2 bb = b2s[((f * 4 + nt) * 4 + kt) * 32 + lane];
                uint32_t br[2] = {bb.x, bb.y};
                mma_f16(g2acc[nt], Ah[kt], br);
            }

        if (!last) {   // h1(t+1), own half — literal acc indices per branch
            float h0, h1;
            if (hh == 0) {
                h0 = ew1(g1acc[0][0], g1acc[1][0], g1acc[2][0], g1acc[3][0], c1[0]);
                h1 = ew1(g1acc[0][1], g1acc[1][1], g1acc[2][1], g1acc[3][1], c1[1]);
            } else {
                h0 = ew1(g1acc[0][2], g1acc[1][2], g1acc[2][2], g1acc[3][2], c1[0]);
                h1 = ew1(g1acc[0][3], g1acc[1][3], g1acc[2][3], g1acc[3][3], c1[1]);
            }
            frag[buf ^ 1][slf] = pack2(h0, h1);
        }
        {   // h2(t), own half
            float h0, h1;
            if (hh == 0) {
                h0 = ew1(g2acc[0][0], g2acc[1][0], g2acc[2][0], g2acc[3][0], c2[0]);
                h1 = ew1(g2acc[0][1], g2acc[1][1], g2acc[2][1], g2acc[3][1], c2[1]);
            } else {
                h0 = ew1(g2acc[0][2], g2acc[1][2], g2acc[2][2], g2acc[3][2], c2[0]);
                h1 = ew1(g2acc[0][3], g2acc[1][3], g2acc[2][3], g2acc[3][3], c2[1]);
            }
            if (!last) {
                frag[buf ^ 1][slf + 256] = pack2(h0, h1);
            } else {
                hf[row][jcol + 0] = h0;
                hf[row][jcol + 1] = h1;
            }
        }
        __syncthreads();
    };

    for (int t = 0; t < Tn; t += 2) {
        phase(t, 0);
        phase(t + 1, 1);
    }

    // ---- FC head ----
    if (tid < NB) {
        float a = fc_b[0];
        #pragma unroll
        for (int k = 0; k < Hn; k++) a = fmaf(hf[tid][k], fc_w[k], a);
        out[b0 + tid] = a;
    }
}

extern "C" void kernel_launch(void* const* d_in, const int* in_sizes, int n_in,
                              void* d_out, int out_size)
{
    (void)in_sizes; (void)n_in; (void)out_size;
    const float* x      = (const float*)d_in[0];
    const float* w_ih_0 = (const float*)d_in[1];
    const float* w_hh_0 = (const float*)d_in[2];
    const float* b_ih_0 = (const float*)d_in[3];
    const float* b_hh_0 = (const float*)d_in[4];
    const float* w_ih_1 = (const float*)d_in[5];
    const float* w_hh_1 = (const float*)d_in[6];
    const float* b_ih_1 = (const float*)d_in[7];
    const float* b_hh_1 = (const float*)d_in[8];
    const float* fc_w   = (const float*)d_in[9];
    const float* fc_b   = (const float*)d_in[10];
    float* o = (float*)d_out;

    dim3 grid(Bn / NB);   // 256 blocks x 256 thr -> 2 blocks/SM, single wave
    dim3 block(NT);
    lstm_tc12<<<grid, block>>>(x, w_ih_0, w_hh_0, b_ih_0, b_hh_0,
                               w_ih_1, w_hh_1, b_ih_1, b_hh_1,
                               fc_w, fc_b, o);
}

// round 16
// speedup vs baseline: 4.1345x; 1.3160x over previous
#include <cuda_runtime.h>
#include <cuda_fp16.h>
#include <stdint.h>

// LSTM_558345748830 v15: split-gate 8-warp groups (work-conserving 4 warps/SMSP).
// Block = 256 thr = 8 warps = 16 batches. Warp w owns ntiles {w, w+8}:
//   w<4 : gates {i,g}, column-family w&3;  w>=4 : gates {f,o}, same family.
// Pair (w, w+4) exchanges the other half's gate PREACTS (f32, exact) via smem;
// each warp runs elementwise for its row half (w<4: rows g, w>=4: rows g+8).
// Per-warp work halves (12 mma, 20 tanh) -> 4 independent warps per SMSP feed
// the binding MUFU pipe. Arithmetic bit-identical to v11.

#define Tn 512
#define Hn 32
#define NB 16
#define NT 256
#define Bn 4096

__device__ __forceinline__ float tanhap(float x) {
    float y;
    asm("tanh.approx.f32 %0, %1;" : "=f"(y) : "f"(x));
    return y;
}
__device__ __forceinline__ float sigap(float x) {
    return fmaf(tanhap(0.5f * x), 0.5f, 0.5f);
}
__device__ __forceinline__ void mma_f16(float* d, const uint32_t* a, const uint32_t* b) {
    asm volatile(
        "mma.sync.aligned.m16n8k16.row.col.f32.f16.f16.f32 "
        "{%0,%1,%2,%3}, {%4,%5,%6,%7}, {%8,%9}, {%0,%1,%2,%3};"
        : "+f"(d[0]), "+f"(d[1]), "+f"(d[2]), "+f"(d[3])
        : "r"(a[0]), "r"(a[1]), "r"(a[2]), "r"(a[3]), "r"(b[0]), "r"(b[1]));
}
// pack {even-k -> low half, odd-k -> high half}
__device__ __forceinline__ uint32_t pack2(float e_even, float e_odd) {
    uint32_t r;
    asm("cvt.rn.f16x2.f32 %0, %1, %2;" : "=r"(r) : "f"(e_odd), "f"(e_even));
    return r;
}

__global__ __launch_bounds__(NT, 2)
void lstm_tc13(const float* __restrict__ x,
               const float* __restrict__ w_ih_0, const float* __restrict__ w_hh_0,
               const float* __restrict__ b_ih_0, const float* __restrict__ b_hh_0,
               const float* __restrict__ w_ih_1, const float* __restrict__ w_hh_1,
               const float* __restrict__ b_ih_1, const float* __restrict__ b_hh_1,
               const float* __restrict__ fc_w,   const float* __restrict__ fc_b,
               float* __restrict__ out)
{
    __shared__ uint32_t frag[2][512];        // [buf][(kt*4+r)*32+lane]; kt0-1=h1, kt2-3=h2
    __shared__ float2   xch[2][8][2][32];    // [layer][warp][nt][lane] gate-preact exchange
    __shared__ float    hf[NB][Hn + 1];      // final h2 for FC head

    const int tid  = threadIdx.x;
    const int lane = tid & 31;
    const int w    = tid >> 5;        // warp 0..7
    const int fam  = w & 3;           // column family
    const int hh   = w >> 2;          // row half: 0 -> rows g, 1 -> rows g+8
    const int g    = lane >> 2;
    const int t4   = lane & 3;
    const int row  = g + 8 * hh;      // batch row this thread's elementwise owns
    const int j0   = 8 * fam + 2 * t4;// hidden-col pair base
    const int pw   = w ^ 4;           // partner warp
    const int b0   = blockIdx.x * NB;
    const float* xg = x + (size_t)b0 * Tn;

    for (int i = tid; i < 2 * 512; i += NT) (&frag[0][0])[i] = 0u;

    // ---- B-fragments in registers: ntile(nt) = w + 8*nt ----
    uint32_t B1[2][2][2];    // layer1 W_hh_0 [nt][ktile][half]
    uint32_t B2[2][4][2];    // layer2 [W_ih_1 | W_hh_1]
    #pragma unroll
    for (int nt = 0; nt < 2; nt++) {
        const int n = (w + 8 * nt) * 8 + g;       // global gate row
        const float* w0 = w_hh_0 + n * Hn;
        #pragma unroll
        for (int kt = 0; kt < 2; kt++)
            #pragma unroll
            for (int h = 0; h < 2; h++) {
                int k = kt * 16 + 2 * t4 + 8 * h;
                B1[nt][kt][h] = pack2(w0[k], w0[k + 1]);
            }
        const float* wi1 = w_ih_1 + n * Hn;
        const float* wh1 = w_hh_1 + n * Hn;
        #pragma unroll
        for (int kt = 0; kt < 4; kt++) {
            const float* ws = (kt < 2) ? (wi1 + kt * 16) : (wh1 + (kt - 2) * 16);
            #pragma unroll
            for (int h = 0; h < 2; h++) {
                int k = 2 * t4 + 8 * h;
                B2[nt][kt][h] = pack2(ws[k], ws[k + 1]);
            }
        }
    }

    // ---- epilogue constants for this thread's gate columns (2 ntiles x parity) ----
    float wx[2][2], bi0[2][2], bi1[2][2];
    #pragma unroll
    for (int nt = 0; nt < 2; nt++)
        #pragma unroll
        for (int e = 0; e < 2; e++) {
            int n = (w + 8 * nt) * 8 + 2 * t4 + e;
            wx[nt][e]  = w_ih_0[n];
            bi0[nt][e] = b_ih_0[n] + b_hh_0[n];
            bi1[nt][e] = b_ih_1[n] + b_hh_1[n];
        }

    // frag store slot: kt = fam>>1, r = 2*(fam&1) + hh; +256 = layer-2 region
    const int slf = (((fam >> 1) * 4) + 2 * (fam & 1) + hh) * 32 + lane;

    float g1acc[2][4], g2acc[2][4];
    float c1[2] = {0.f, 0.f}, c2[2] = {0.f, 0.f};

    auto ew1 = [&](float gi, float gf, float gg, float go, float& c) -> float {
        float i_ = sigap(gi);
        float f_ = sigap(gf);
        float g_ = tanhap(gg);
        float o_ = sigap(go);
        c = fmaf(f_, c, i_ * g_);
        return o_ * tanhap(c);
    };

    // ---- prologue: h1(0) computed directly per element (no mma, no exchange) ----
    {
        const float xv = __ldg(&xg[row * Tn]);
        float hv[2];
        #pragma unroll
        for (int e = 0; e < 2; e++) {
            const int j = j0 + e;
            float gi = fmaf(w_ih_0[j],           xv, b_ih_0[j]           + b_hh_0[j]);
            float gf = fmaf(w_ih_0[Hn + j],      xv, b_ih_0[Hn + j]      + b_hh_0[Hn + j]);
            float gg = fmaf(w_ih_0[2 * Hn + j],  xv, b_ih_0[2 * Hn + j]  + b_hh_0[2 * Hn + j]);
            float go = fmaf(w_ih_0[3 * Hn + j],  xv, b_ih_0[3 * Hn + j]  + b_hh_0[3 * Hn + j]);
            hv[e] = ew1(gi, gf, gg, go, c1[e]);
        }
        frag[0][slf] = pack2(hv[0], hv[1]);
        // h2(-1) region already zero
    }
    __syncthreads();

    // ---- one fused phase; buf literal -> constant frag addrs ----
    auto phase = [&](const int t, const int buf) {
        const bool last = (t == Tn - 1);
        uint32_t Ah[4][4];
        #pragma unroll
        for (int kt = 0; kt < 4; kt++)
            #pragma unroll
            for (int r = 0; r < 4; r++)
                Ah[kt][r] = frag[buf][(kt * 4 + r) * 32 + lane];

        if (!last) {   // gates1(t+1) for this warp's 2 ntiles, ALL 16 rows
            const float xv0 = __ldg(&xg[g * Tn + t + 1]);
            const float xv1 = __ldg(&xg[(g + 8) * Tn + t + 1]);
            #pragma unroll
            for (int nt = 0; nt < 2; nt++) {
                g1acc[nt][0] = fmaf(wx[nt][0], xv0, bi0[nt][0]);
                g1acc[nt][1] = fmaf(wx[nt][1], xv0, bi0[nt][1]);
                g1acc[nt][2] = fmaf(wx[nt][0], xv1, bi0[nt][0]);
                g1acc[nt][3] = fmaf(wx[nt][1], xv1, bi0[nt][1]);
                #pragma unroll
                for (int kt = 0; kt < 2; kt++)
                    mma_f16(g1acc[nt], Ah[kt], B1[nt][kt]);
            }
        }
        // gates2(t)
        #pragma unroll
        for (int nt = 0; nt < 2; nt++) {
            g2acc[nt][0] = bi1[nt][0];
            g2acc[nt][1] = bi1[nt][1];
            g2acc[nt][2] = bi1[nt][0];
            g2acc[nt][3] = bi1[nt][1];
            #pragma unroll
            for (int kt = 0; kt < 4; kt++)
                mma_f16(g2acc[nt], Ah[kt], B2[nt][kt]);
        }

        // ---- store partner's row-half gate preacts (f32, exact) ----
        if (hh == 0) {   // I process rows g; partner needs rows g+8 -> d2,d3
            if (!last) {
                xch[0][w][0][lane] = make_float2(g1acc[0][2], g1acc[0][3]);
                xch[0][w][1][lane] = make_float2(g1acc[1][2], g1acc[1][3]);
            }
            xch[1][w][0][lane] = make_float2(g2acc[0][2], g2acc[0][3]);
            xch[1][w][1][lane] = make_float2(g2acc[1][2], g2acc[1][3]);
        } else {         // I process rows g+8; partner needs rows g -> d0,d1
            if (!last) {
                xch[0][w][0][lane] = make_float2(g1acc[0][0], g1acc[0][1]);
                xch[0][w][1][lane] = make_float2(g1acc[1][0], g1acc[1][1]);
            }
            xch[1][w][0][lane] = make_float2(g2acc[0][0], g2acc[0][1]);
            xch[1][w][1][lane] = make_float2(g2acc[1][0], g2acc[1][1]);
        }
        __syncthreads();

        // ---- elementwise: layer 1 (h1(t+1)) ----
        if (!last) {
            float2 xa = xch[0][pw][0][lane];
            float2 xb = xch[0][pw][1][lane];
            float h0, h1;
            if (hh == 0) {   // own: i=acc0, g=acc1 (rows g -> d0,d1); xch: f,o
                h0 = ew1(g1acc[0][0], xa.x, g1acc[1][0], xb.x, c1[0]);
                h1 = ew1(g1acc[0][1], xa.y, g1acc[1][1], xb.y, c1[1]);
            } else {         // own: f=acc0, o=acc1 (rows g+8 -> d2,d3); xch: i,g
                h0 = ew1(xa.x, g1acc[0][2], xb.x, g1acc[1][2], c1[0]);
                h1 = ew1(xa.y, g1acc[0][3], xb.y, g1acc[1][3], c1[1]);
            }
            frag[buf ^ 1][slf] = pack2(h0, h1);
        }
        // ---- elementwise: layer 2 (h2(t)) ----
        {
            float2 xa = xch[1][pw][0][lane];
            float2 xb = xch[1][pw][1][lane];
            float h0, h1;
            if (hh == 0) {
                h0 = ew1(g2acc[0][0], xa.x, g2acc[1][0], xb.x, c2[0]);
                h1 = ew1(g2acc[0][1], xa.y, g2acc[1][1], xb.y, c2[1]);
            } else {
                h0 = ew1(xa.x, g2acc[0][2], xb.x, g2acc[1][2], c2[0]);
                h1 = ew1(xa.y, g2acc[0][3], xb.y, g2acc[1][3], c2[1]);
            }
            if (!last) {
                frag[buf ^ 1][slf + 256] = pack2(h0, h1);
            } else {
                hf[row][j0 + 0] = h0;
                hf[row][j0 + 1] = h1;
            }
        }
        __syncthreads();
    };

    for (int t = 0; t < Tn; t += 2) {
        phase(t, 0);
        phase(t + 1, 1);
    }

    // ---- FC head ----
    if (tid < NB) {
        float a = fc_b[0];
        #pragma unroll
        for (int k = 0; k < Hn; k++) a = fmaf(hf[tid][k], fc_w[k], a);
        out[b0 + tid] = a;
    }
}

extern "C" void kernel_launch(void* const* d_in, const int* in_sizes, int n_in,
                              void* d_out, int out_size)
{
    (void)in_sizes; (void)n_in; (void)out_size;
    const float* x      = (const float*)d_in[0];
    const float* w_ih_0 = (const float*)d_in[1];
    const float* w_hh_0 = (const float*)d_in[2];
    const float* b_ih_0 = (const float*)d_in[3];
    const float* b_hh_0 = (const float*)d_in[4];
    const float* w_ih_1 = (const float*)d_in[5];
    const float* w_hh_1 = (const float*)d_in[6];
    const float* b_ih_1 = (const float*)d_in[7];
    const float* b_hh_1 = (const float*)d_in[8];
    const float* fc_w   = (const float*)d_in[9];
    const float* fc_b   = (const float*)d_in[10];
    float* o = (float*)d_out;

    dim3 grid(Bn / NB);   // 256 blocks x 256 thr -> 2 blocks/SM, single wave
    dim3 block(NT);
    lstm_tc13<<<grid, block>>>(x, w_ih_0, w_hh_0, b_ih_0, b_hh_0,
                               w_ih_1, w_hh_1, b_ih_1, b_hh_1,
                               fc_w, fc_b, o);
}

// round 17
// speedup vs baseline: 5.5953x; 1.3533x over previous
#include <cuda_runtime.h>
#include <cuda_fp16.h>
#include <stdint.h>

// LSTM_558345748830 v16: v11 + vectorized frag exchange (LDS.64/STS.64 paired
// layout) + transposed smem x-slab (kills the 16-line LDG pattern).
// Block = 128 thr = 4 warps = 16 batches; warp w owns gate ntiles {w,w+4,w+8,w+12}
// (ntile == gate) -> all 4 gates live in each thread's mma accumulators.
// One fused phase + one barrier per step. Math bit-identical to v11.

#define Tn 512
#define Hn 32
#define NB 16
#define NT 128
#define Bn 4096

__device__ __forceinline__ float tanhap(float x) {
    float y;
    asm("tanh.approx.f32 %0, %1;" : "=f"(y) : "f"(x));
    return y;
}
__device__ __forceinline__ float sigap(float x) {
    return fmaf(tanhap(0.5f * x), 0.5f, 0.5f);
}
__device__ __forceinline__ void mma_f16(float* d, const uint32_t* a, const uint32_t* b) {
    asm volatile(
        "mma.sync.aligned.m16n8k16.row.col.f32.f16.f16.f32 "
        "{%0,%1,%2,%3}, {%4,%5,%6,%7}, {%8,%9}, {%0,%1,%2,%3};"
        : "+f"(d[0]), "+f"(d[1]), "+f"(d[2]), "+f"(d[3])
        : "r"(a[0]), "r"(a[1]), "r"(a[2]), "r"(a[3]), "r"(b[0]), "r"(b[1]));
}
// pack {even-k -> low half, odd-k -> high half}
__device__ __forceinline__ uint32_t pack2(float e_even, float e_odd) {
    uint32_t r;
    asm("cvt.rn.f16x2.f32 %0, %1, %2;" : "=r"(r) : "f"(e_odd), "f"(e_even));
    return r;
}

__global__ __launch_bounds__(NT, 2)
void lstm_tc14(const float* __restrict__ x,
               const float* __restrict__ w_ih_0, const float* __restrict__ w_hh_0,
               const float* __restrict__ b_ih_0, const float* __restrict__ b_hh_0,
               const float* __restrict__ w_ih_1, const float* __restrict__ w_hh_1,
               const float* __restrict__ b_ih_1, const float* __restrict__ b_hh_1,
               const float* __restrict__ fc_w,   const float* __restrict__ fc_b,
               float* __restrict__ out)
{
    // frag layout (paired): slot = (kt*2 + p)*64 + 2*lane + rr
    //   kt = ktile (0-1: h1, 2-3: h2), p = k-half (a0a1 vs a2a3), rr = row g / g+8
    __shared__ uint32_t frag[2][512];
    __shared__ float    xs[Tn][17];      // transposed x slab: xs[t][b], padded
    __shared__ float    hf[NB][Hn + 1];  // final h2 for FC head

    const int tid  = threadIdx.x;
    const int lane = tid & 31;
    const int w    = tid >> 5;        // warp 0..3
    const int g    = lane >> 2;       // mma group row 0..7
    const int t4   = lane & 3;
    const int b0   = blockIdx.x * NB;
    const float* xg = x + (size_t)b0 * Tn;

    for (int i = tid; i < 2 * 512; i += NT) (&frag[0][0])[i] = 0u;

    // ---- x slab: coalesced load, transposed store ----
    for (int it = tid; it < NB * Tn / 4; it += NT) {
        int b  = it >> 7;             // 0..15
        int t0 = (it & 127) * 4;      // 0..508
        float4 v = *(const float4*)(xg + b * Tn + t0);
        xs[t0 + 0][b] = v.x;
        xs[t0 + 1][b] = v.y;
        xs[t0 + 2][b] = v.z;
        xs[t0 + 3][b] = v.w;
    }

    // ---- weight B-fragments (fp16); ntile(nt) = w + 4*nt = gate index ----
    uint32_t B1[4][2][2];    // layer1 W_hh_0 [gate][ktile][half]
    uint32_t B2[4][4][2];    // layer2 [W_ih_1 | W_hh_1]
    #pragma unroll
    for (int nt = 0; nt < 4; nt++) {
        const int n = (w + 4 * nt) * 8 + g;       // global gate row
        const float* w0 = w_hh_0 + n * Hn;
        #pragma unroll
        for (int kt = 0; kt < 2; kt++)
            #pragma unroll
            for (int h = 0; h < 2; h++) {
                int k = kt * 16 + 2 * t4 + 8 * h;
                B1[nt][kt][h] = pack2(w0[k], w0[k + 1]);
            }
        const float* wi1 = w_ih_1 + n * Hn;
        const float* wh1 = w_hh_1 + n * Hn;
        #pragma unroll
        for (int kt = 0; kt < 4; kt++) {
            const float* ws = (kt < 2) ? (wi1 + kt * 16) : (wh1 + (kt - 2) * 16);
            #pragma unroll
            for (int h = 0; h < 2; h++) {
                int k = 2 * t4 + 8 * h;
                B2[nt][kt][h] = pack2(ws[k], ws[k + 1]);
            }
        }
    }

    // ---- epilogue constants per (gate nt, parity) ----
    float wx[8], bi0[8], bi1[8];
    #pragma unroll
    for (int q = 0; q < 8; q++) {
        int n = (w + 4 * (q >> 1)) * 8 + 2 * t4 + (q & 1);
        wx[q]  = w_ih_0[n];
        bi0[q] = b_ih_0[n] + b_hh_0[n];
        bi1[q] = b_ih_1[n] + b_hh_1[n];
    }

    // paired frag store base for this thread's (rows g,g+8) x (cols j,j+1):
    // kt = w>>1, p = w&1  ->  base = ((w>>1)*2 + (w&1))*64 + 2*lane
    const int base2 = (((w >> 1) * 2) + (w & 1)) * 64 + 2 * lane;
    const int j     = 8 * w + 2 * t4;

    float g1acc[4][4], g2acc[4][4];   // [gate][p]
    float c1[4] = {0.f, 0.f, 0.f, 0.f};
    float c2[4] = {0.f, 0.f, 0.f, 0.f};

    __syncthreads();   // xs slab ready

    // ---- prologue: gates1(0) -> h1(0) -> frag[0] ----
    {
        const float xv0 = xs[0][g];
        const float xv1 = xs[0][g + 8];
        #pragma unroll
        for (int nt = 0; nt < 4; nt++) {
            g1acc[nt][0] = fmaf(wx[nt * 2 + 0], xv0, bi0[nt * 2 + 0]);
            g1acc[nt][1] = fmaf(wx[nt * 2 + 1], xv0, bi0[nt * 2 + 1]);
            g1acc[nt][2] = fmaf(wx[nt * 2 + 0], xv1, bi0[nt * 2 + 0]);
            g1acc[nt][3] = fmaf(wx[nt * 2 + 1], xv1, bi0[nt * 2 + 1]);
        }
        float h1v[4];
        #pragma unroll
        for (int p = 0; p < 4; p++) {
            float i_ = sigap(g1acc[0][p]);
            float f_ = sigap(g1acc[1][p]);
            float g_ = tanhap(g1acc[2][p]);
            float o_ = sigap(g1acc[3][p]);
            c1[p] = fmaf(f_, c1[p], i_ * g_);
            h1v[p] = o_ * tanhap(c1[p]);
        }
        uint2 hv;
        hv.x = pack2(h1v[0], h1v[1]);   // row g
        hv.y = pack2(h1v[2], h1v[3]);   // row g+8
        *(uint2*)&frag[0][base2] = hv;
        // h2(-1) region already zero
    }
    __syncthreads();

    // ---- one fused phase; buf literal -> constant frag addrs ----
    auto phase = [&](const int t, const int buf) {
        const bool last = (t == Tn - 1);
        uint32_t Ah[4][4];
        #pragma unroll
        for (int kt = 0; kt < 4; kt++) {
            uint2 v0 = *(const uint2*)&frag[buf][(kt * 2 + 0) * 64 + 2 * lane];
            uint2 v1 = *(const uint2*)&frag[buf][(kt * 2 + 1) * 64 + 2 * lane];
            Ah[kt][0] = v0.x;   // a0: row g,   k-lo
            Ah[kt][1] = v0.y;   // a1: row g+8, k-lo
            Ah[kt][2] = v1.x;   // a2: row g,   k-hi
            Ah[kt][3] = v1.y;   // a3: row g+8, k-hi
        }

        if (!last) {   // gates1(t+1)
            const float xv0 = xs[t + 1][g];
            const float xv1 = xs[t + 1][g + 8];
            #pragma unroll
            for (int nt = 0; nt < 4; nt++) {
                g1acc[nt][0] = fmaf(wx[nt * 2 + 0], xv0, bi0[nt * 2 + 0]);
                g1acc[nt][1] = fmaf(wx[nt * 2 + 1], xv0, bi0[nt * 2 + 1]);
                g1acc[nt][2] = fmaf(wx[nt * 2 + 0], xv1, bi0[nt * 2 + 0]);
                g1acc[nt][3] = fmaf(wx[nt * 2 + 1], xv1, bi0[nt * 2 + 1]);
                #pragma unroll
                for (int kt = 0; kt < 2; kt++)
                    mma_f16(g1acc[nt], Ah[kt], B1[nt][kt]);
            }
        }
        // gates2(t)
        #pragma unroll
        for (int nt = 0; nt < 4; nt++) {
            g2acc[nt][0] = bi1[nt * 2 + 0];
            g2acc[nt][1] = bi1[nt * 2 + 1];
            g2acc[nt][2] = bi1[nt * 2 + 0];
            g2acc[nt][3] = bi1[nt * 2 + 1];
            #pragma unroll
            for (int kt = 0; kt < 4; kt++)
                mma_f16(g2acc[nt], Ah[kt], B2[nt][kt]);
        }

        if (!last) {   // h1(t+1): depends only on g1acc -> overlaps g2 mma
            float h1v[4];
            #pragma unroll
            for (int p = 0; p < 4; p++) {
                float i_ = sigap(g1acc[0][p]);
                float f_ = sigap(g1acc[1][p]);
                float g_ = tanhap(g1acc[2][p]);
                float o_ = sigap(g1acc[3][p]);
                c1[p] = fmaf(f_, c1[p], i_ * g_);
                h1v[p] = o_ * tanhap(c1[p]);
            }
            uint2 hv;
            hv.x = pack2(h1v[0], h1v[1]);
            hv.y = pack2(h1v[2], h1v[3]);
            *(uint2*)&frag[buf ^ 1][base2] = hv;
        }
        {   // h2(t)
            float h2v[4];
            #pragma unroll
            for (int p = 0; p < 4; p++) {
                float i_ = sigap(g2acc[0][p]);
                float f_ = sigap(g2acc[1][p]);
                float g_ = tanhap(g2acc[2][p]);
                float o_ = sigap(g2acc[3][p]);
                c2[p] = fmaf(f_, c2[p], i_ * g_);
                h2v[p] = o_ * tanhap(c2[p]);
            }
            if (!last) {
                uint2 hv;
                hv.x = pack2(h2v[0], h2v[1]);
                hv.y = pack2(h2v[2], h2v[3]);
                *(uint2*)&frag[buf ^ 1][base2 + 256] = hv;
            } else {
                #pragma unroll
                for (int p = 0; p < 4; p++)
                    hf[(p < 2) ? g : (g + 8)][j + (p & 1)] = h2v[p];
            }
        }
        __syncthreads();
    };

    for (int t = 0; t < Tn; t += 2) {
        phase(t, 0);
        phase(t + 1, 1);
    }

    // ---- FC head ----
    if (tid < NB) {
        float a = fc_b[0];
        #pragma unroll
        for (int k = 0; k < Hn; k++) a = fmaf(hf[tid][k], fc_w[k], a);
        out[b0 + tid] = a;
    }
}

extern "C" void kernel_launch(void* const* d_in, const int* in_sizes, int n_in,
                              void* d_out, int out_size)
{
    (void)in_sizes; (void)n_in; (void)out_size;
    const float* x      = (const float*)d_in[0];
    const float* w_ih_0 = (const float*)d_in[1];
    const float* w_hh_0 = (const float*)d_in[2];
    const float* b_ih_0 = (const float*)d_in[3];
    const float* b_hh_0 = (const float*)d_in[4];
    const float* w_ih_1 = (const float*)d_in[5];
    const float* w_hh_1 = (const float*)d_in[6];
    const float* b_ih_1 = (const float*)d_in[7];
    const float* b_hh_1 = (const float*)d_in[8];
    const float* fc_w   = (const float*)d_in[9];
    const float* fc_b   = (const float*)d_in[10];
    float* o = (float*)d_out;

    dim3 grid(Bn / NB);   // 256 blocks x 128 thr -> 2 blocks/SM, single wave
    dim3 block(NT);
    lstm_tc14<<<grid, block>>>(x, w_ih_0, w_hh_0, b_ih_0, b_hh_0,
                               w_ih_1, w_hh_1, b_ih_1, b_hh_1,
                               fc_w, fc_b, o);
}